// round 4
// baseline (speedup 1.0000x reference)
#include <cuda_runtime.h>

#define EPSV 1e-8f

// One block = 32 queries x 32 weight rows, all 8 sub-vectors, fully fused.
// Grid = 16 b-tiles * 8 r-tiles = 128 blocks, 256 threads (16x16, 2x2 reg blocking).
__global__ __launch_bounds__(256) void fused_kernel(const float* __restrict__ q,
                                                    const float* __restrict__ w,
                                                    float* __restrict__ out)
{
    __shared__ union {
        struct {
            float4 qs[32][33];
            float4 ws[32][33];
        } t;                          // 33.8 KB, phase 1
        float cs[32 * 32 * 8];        // 32 KB, phase 2: [pair][n]
    } S;
    __shared__ float inv_qn_s[32];
    __shared__ float inv_wn_s[32];

    const int tid  = threadIdx.x;
    const int tx   = tid & 15, ty = tid >> 4;
    const int warp = tid >> 5, lane = tid & 31;
    const int b0 = (blockIdx.x >> 3) * 32;
    const int r0 = (blockIdx.x & 7) * 32;

    const float4* q4 = (const float4*)q;
    const float4* w4 = (const float4*)w;

    float csr[8][4];   // [n][dy*2+dx]

    // ======================= Phase 1: dots + norms ========================
    for (int n = 0; n < 8; n++) {
        __syncthreads();
#pragma unroll
        for (int k = 0; k < 4; k++) {
            int idx = tid + 256 * k;
            int row = idx >> 5, col = idx & 31;
            S.t.qs[row][col] = q4[(size_t)(b0 + row) * 256 + n * 32 + col];
            S.t.ws[row][col] = w4[(size_t)(r0 + row) * 256 + n * 32 + col];
        }
        __syncthreads();

        // ---- row norms from staged tiles: 4 threads per row ----
        {
            int rowid = tid >> 2;       // 0..63 (0-31 q, 32-63 w)
            int sub   = tid & 3;
            const float4* src = (rowid < 32) ? &S.t.qs[rowid][0]
                                             : &S.t.ws[rowid - 32][0];
            float s = 0.f;
#pragma unroll
            for (int j = 0; j < 8; j++) {
                float4 v = src[sub * 8 + j];
                s = fmaf(v.x, v.x, fmaf(v.y, v.y, fmaf(v.z, v.z, fmaf(v.w, v.w, s))));
            }
            s += __shfl_xor_sync(0xffffffffu, s, 1);
            s += __shfl_xor_sync(0xffffffffu, s, 2);
            if (sub == 0) {
                float inv = 1.0f / fmaxf(sqrtf(s), EPSV);
                if (rowid < 32) inv_qn_s[rowid] = inv;
                else            inv_wn_s[rowid - 32] = inv;
            }
        }
        __syncthreads();

        // ---- 2x2 register-blocked dot over K=128 ----
        float a00 = 0.f, a01 = 0.f, a10 = 0.f, a11 = 0.f;
#pragma unroll
        for (int k = 0; k < 32; k++) {
            float4 qa = S.t.qs[2 * ty + 0][k];
            float4 qb = S.t.qs[2 * ty + 1][k];
            float4 wa = S.t.ws[2 * tx + 0][k];
            float4 wb = S.t.ws[2 * tx + 1][k];
            a00 = fmaf(qa.x, wa.x, fmaf(qa.y, wa.y, fmaf(qa.z, wa.z, fmaf(qa.w, wa.w, a00))));
            a01 = fmaf(qa.x, wb.x, fmaf(qa.y, wb.y, fmaf(qa.z, wb.z, fmaf(qa.w, wb.w, a01))));
            a10 = fmaf(qb.x, wa.x, fmaf(qb.y, wa.y, fmaf(qb.z, wa.z, fmaf(qb.w, wa.w, a10))));
            a11 = fmaf(qb.x, wb.x, fmaf(qb.y, wb.y, fmaf(qb.z, wb.z, fmaf(qb.w, wb.w, a11))));
        }

        float iq0 = inv_qn_s[2 * ty + 0];
        float iq1 = inv_qn_s[2 * ty + 1];
        float iw0 = inv_wn_s[2 * tx + 0];
        float iw1 = inv_wn_s[2 * tx + 1];
        csr[n][0] = fmaxf(a00 * iq0 * iw0, 0.f);
        csr[n][1] = fmaxf(a01 * iq0 * iw1, 0.f);
        csr[n][2] = fmaxf(a10 * iq1 * iw0, 0.f);
        csr[n][3] = fmaxf(a11 * iq1 * iw1, 0.f);
    }

    // =================== redistribute cs through smem =====================
    __syncthreads();   // everyone done reading qs/ws
#pragma unroll
    for (int m = 0; m < 4; m++) {
        int dy = m >> 1, dx = m & 1;
        int pair = (2 * ty + dy) * 32 + (2 * tx + dx);
        float4 lo = make_float4(csr[0][m], csr[1][m], csr[2][m], csr[3][m]);
        float4 hi = make_float4(csr[4][m], csr[5][m], csr[6][m], csr[7][m]);
        float4* d = (float4*)&S.cs[pair * 8];
        d[0] = lo;
        d[1] = hi;
    }
    __syncthreads();

    // ===================== Phase 2: expansion + store =====================
    // warp handles pairs p = warp*128 .. warp*128+127; lane covers i = lane*8+m
#pragma unroll 4
    for (int it = 0; it < 128; it++) {
        int p = warp * 128 + it;
        float4 cA = ((const float4*)&S.cs[p * 8])[0];   // broadcast
        float4 cB = ((const float4*)&S.cs[p * 8])[1];

        float cs0 = cA.x, cs1 = cA.y, cs2 = cA.z, cs3 = cA.w;
        float cs4 = cB.x, cs5 = cB.y, cs6 = cB.z, cs7 = cB.w;
        float ms0 = 1.f - cs0, ms1 = 1.f - cs1, ms2 = 1.f - cs2, ms3 = 1.f - cs3;
        float ms4 = 1.f - cs4, ms5 = 1.f - cs5, ms6 = 1.f - cs6, ms7 = 1.f - cs7;

        // bits 3..7 of i come from lane bits 0..4
        float base = ((lane >> 0) & 1 ? ms3 : cs3);
        base *= ((lane >> 1) & 1 ? ms4 : cs4);
        base *= ((lane >> 2) & 1 ? ms5 : cs5);
        base *= ((lane >> 3) & 1 ? ms6 : cs6);
        base *= ((lane >> 4) & 1 ? ms7 : cs7);

        float p0 = cs0 * cs1, p1 = ms0 * cs1, p2 = cs0 * ms1, p3 = ms0 * ms1;
        float b2c = base * cs2, b2m = base * ms2;

        float4 o0, o1;
        o0.x = b2c * p0;  o0.y = b2c * p1;  o0.z = b2c * p2;  o0.w = b2c * p3;
        o1.x = b2m * p0;  o1.y = b2m * p1;  o1.z = b2m * p2;  o1.w = b2m * p3;

        int brow = p >> 5, rrow = p & 31;
        float4* dst = (float4*)(out + ((size_t)(b0 + brow) * 256 + (r0 + rrow)) * 256
                                + lane * 8);
        __stcs(dst, o0);
        __stcs(dst + 1, o1);
    }
}

extern "C" void kernel_launch(void* const* d_in, const int* in_sizes, int n_in,
                              void* d_out, int out_size) {
    const float* q = (const float*)d_in[0];   // 512 x 1024
    const float* w = (const float*)d_in[1];   // 256 x 1024
    float* out = (float*)d_out;               // 512 x 256 x 256

    fused_kernel<<<128, 256>>>(q, w, out);
}

// round 7
// speedup vs baseline: 1.1467x; 1.1467x over previous
#include <cuda_runtime.h>

#define EPSV 1e-8f

// scratch: cs[b][r][n] = relu(cosine), 4 MB (lives in L2 between kernels)
__device__ __align__(16) float g_cs[512 * 256 * 8];

// ---------------------------------------------------------------------------
// cs kernel: one (32b x 32r, n) slice per block. Grid (128, 8) = 1024 blocks.
// 256 threads (16x16), 2x2 register blocking. Norms computed in-block from
// the staged tiles (no separate norm kernel, no global norm round-trip).
// ---------------------------------------------------------------------------
__global__ __launch_bounds__(256) void cs_kernel(const float* __restrict__ q,
                                                 const float* __restrict__ w)
{
    __shared__ float4 qs[32][33];
    __shared__ float4 ws[32][33];
    __shared__ float inv_qn_s[32];
    __shared__ float inv_wn_s[32];

    const int tid = threadIdx.x;
    const int tx = tid & 15, ty = tid >> 4;
    const int b0 = (blockIdx.x >> 3) * 32;
    const int r0 = (blockIdx.x & 7) * 32;
    const int n  = blockIdx.y;

    const float4* q4 = (const float4*)q;
    const float4* w4 = (const float4*)w;

    // ---- stage 32x128 q and w sub-tiles (coalesced float4) ----
#pragma unroll
    for (int k = 0; k < 4; k++) {
        int idx = tid + 256 * k;
        int row = idx >> 5, col = idx & 31;
        qs[row][col] = q4[(size_t)(b0 + row) * 256 + n * 32 + col];
        ws[row][col] = w4[(size_t)(r0 + row) * 256 + n * 32 + col];
    }
    __syncthreads();

    // ---- in-block row norms: 4 threads per row (64 rows: 32 q + 32 w) ----
    {
        int rowid = tid >> 2;      // 0..63
        int sub   = tid & 3;
        const float4* src = (rowid < 32) ? &qs[rowid][0] : &ws[rowid - 32][0];
        float s = 0.f;
#pragma unroll
        for (int j = 0; j < 8; j++) {
            float4 v = src[sub * 8 + j];
            s = fmaf(v.x, v.x, fmaf(v.y, v.y, fmaf(v.z, v.z, fmaf(v.w, v.w, s))));
        }
        s += __shfl_xor_sync(0xffffffffu, s, 1);
        s += __shfl_xor_sync(0xffffffffu, s, 2);
        if (sub == 0) {
            float inv = 1.0f / fmaxf(sqrtf(s), EPSV);
            if (rowid < 32) inv_qn_s[rowid] = inv;
            else            inv_wn_s[rowid - 32] = inv;
        }
    }
    __syncthreads();

    // ---- 2x2 register-blocked dot over K=128 ----
    float a00 = 0.f, a01 = 0.f, a10 = 0.f, a11 = 0.f;
#pragma unroll
    for (int k = 0; k < 32; k++) {
        float4 qa = qs[2 * ty + 0][k];
        float4 qb = qs[2 * ty + 1][k];
        float4 wa = ws[2 * tx + 0][k];
        float4 wb = ws[2 * tx + 1][k];
        a00 = fmaf(qa.x, wa.x, fmaf(qa.y, wa.y, fmaf(qa.z, wa.z, fmaf(qa.w, wa.w, a00))));
        a01 = fmaf(qa.x, wb.x, fmaf(qa.y, wb.y, fmaf(qa.z, wb.z, fmaf(qa.w, wb.w, a01))));
        a10 = fmaf(qb.x, wa.x, fmaf(qb.y, wa.y, fmaf(qb.z, wa.z, fmaf(qb.w, wa.w, a10))));
        a11 = fmaf(qb.x, wb.x, fmaf(qb.y, wb.y, fmaf(qb.z, wb.z, fmaf(qb.w, wb.w, a11))));
    }

    float iq0 = inv_qn_s[2 * ty + 0];
    float iq1 = inv_qn_s[2 * ty + 1];
    float iw0 = inv_wn_s[2 * tx + 0];
    float iw1 = inv_wn_s[2 * tx + 1];

    size_t base0 = ((size_t)(b0 + 2 * ty + 0) * 256 + (r0 + 2 * tx)) * 8 + n;
    size_t base1 = ((size_t)(b0 + 2 * ty + 1) * 256 + (r0 + 2 * tx)) * 8 + n;
    g_cs[base0]     = fmaxf(a00 * iq0 * iw0, 0.f);
    g_cs[base0 + 8] = fmaxf(a01 * iq0 * iw1, 0.f);
    g_cs[base1]     = fmaxf(a10 * iq1 * iw0, 0.f);
    g_cs[base1 + 8] = fmaxf(a11 * iq1 * iw1, 0.f);
}

// ---------------------------------------------------------------------------
// expand kernel: 1024 blocks x 256 threads. Block owns 128 consecutive pairs
// (128 KB contiguous output). Stage the block's 4 KB of cs into smem once,
// then each warp emits 16 pairs with broadcast LDS + ~25 FLOPs + 2 STG.128.
// ---------------------------------------------------------------------------
__global__ __launch_bounds__(256) void expand_kernel(float* __restrict__ out)
{
    __shared__ float s_cs[128 * 8];

    const int tid  = threadIdx.x;
    const int warp = tid >> 5;
    const int lane = tid & 31;
    const size_t p0 = (size_t)blockIdx.x * 128;   // first pair of this block

    // stage cs slice: 1024 floats = 256 float4, fully coalesced
    ((float4*)s_cs)[tid] = ((const float4*)(g_cs + p0 * 8))[tid];
    __syncthreads();

    // lane-dependent selectors for bits 3..7 (hoisted out of the loop)
    const int s3 = (lane >> 0) & 1, s4 = (lane >> 1) & 1, s5 = (lane >> 2) & 1;
    const int s6 = (lane >> 3) & 1, s7 = (lane >> 4) & 1;

    float* outw = out + (p0 + warp * 16) * 256 + lane * 8;

#pragma unroll 4
    for (int j = 0; j < 16; j++) {
        const float* c = &s_cs[(warp * 16 + j) * 8];
        float4 cA = ((const float4*)c)[0];   // broadcast LDS
        float4 cB = ((const float4*)c)[1];

        float cs0 = cA.x, cs1 = cA.y, cs2 = cA.z, cs3 = cA.w;
        float cs4 = cB.x, cs5 = cB.y, cs6 = cB.z, cs7 = cB.w;
        float ms0 = 1.f - cs0, ms1 = 1.f - cs1, ms2 = 1.f - cs2;

        float base = (s3 ? 1.f - cs3 : cs3);
        base *= (s4 ? 1.f - cs4 : cs4);
        base *= (s5 ? 1.f - cs5 : cs5);
        base *= (s6 ? 1.f - cs6 : cs6);
        base *= (s7 ? 1.f - cs7 : cs7);

        float q0 = cs0 * cs1, q1 = ms0 * cs1, q2 = cs0 * ms1, q3 = ms0 * ms1;
        float b2c = base * cs2, b2m = base * ms2;

        float4 o0, o1;
        o0.x = b2c * q0;  o0.y = b2c * q1;  o0.z = b2c * q2;  o0.w = b2c * q3;
        o1.x = b2m * q0;  o1.y = b2m * q1;  o1.z = b2m * q2;  o1.w = b2m * q3;

        float4* dst = (float4*)(outw + (size_t)j * 256);
        dst[0] = o0;
        dst[1] = o1;
    }
}

extern "C" void kernel_launch(void* const* d_in, const int* in_sizes, int n_in,
                              void* d_out, int out_size) {
    const float* q = (const float*)d_in[0];   // 512 x 1024
    const float* w = (const float*)d_in[1];   // 256 x 1024
    float* out = (float*)d_out;               // 512 x 256 x 256

    cs_kernel<<<dim3(128, 8), 256>>>(q, w);
    expand_kernel<<<1024, 256>>>(out);
}

// round 10
// speedup vs baseline: 1.7212x; 1.5011x over previous
#include <cuda_runtime.h>

#define EPSV 1e-8f

// scratch: cs[b][r][n] = relu(cosine), 4 MB (stays in L2 between kernels)
__device__ __align__(16) float g_cs[512 * 256 * 8];

// ---------------------------------------------------------------------------
// cs kernel: one (32b x 32r, n) slice per block. Grid (128, 8) = 1024 blocks.
// 256 threads (16x16), 2x2 register blocking with ROW-INTERLEAVED blocks
// ({tx, tx+16} / {ty, ty+16}) so the w-tile LDS.128 are only 2-way conflicted
// (the structural minimum), instead of 4-way with {2tx, 2tx+1}.
// ---------------------------------------------------------------------------
__global__ __launch_bounds__(256) void cs_kernel(const float* __restrict__ q,
                                                 const float* __restrict__ w)
{
    __shared__ float4 qs[32][33];
    __shared__ float4 ws[32][33];
    __shared__ float inv_qn_s[32];
    __shared__ float inv_wn_s[32];

    const int tid = threadIdx.x;
    const int tx = tid & 15, ty = tid >> 4;
    const int b0 = (blockIdx.x >> 3) * 32;
    const int r0 = (blockIdx.x & 7) * 32;
    const int n  = blockIdx.y;

    const float4* q4 = (const float4*)q;
    const float4* w4 = (const float4*)w;

    // ---- stage 32x128 q and w sub-tiles (coalesced float4) ----
#pragma unroll
    for (int k = 0; k < 4; k++) {
        int idx = tid + 256 * k;
        int row = idx >> 5, col = idx & 31;
        qs[row][col] = q4[(size_t)(b0 + row) * 256 + n * 32 + col];
        ws[row][col] = w4[(size_t)(r0 + row) * 256 + n * 32 + col];
    }
    __syncthreads();

    // ---- in-block row norms: 4 threads per row (64 rows: 32 q + 32 w) ----
    {
        int rowid = tid >> 2;      // 0..63
        int sub   = tid & 3;
        const float4* src = (rowid < 32) ? &qs[rowid][0] : &ws[rowid - 32][0];
        float s = 0.f;
#pragma unroll
        for (int j = 0; j < 8; j++) {
            float4 v = src[sub * 8 + j];
            s = fmaf(v.x, v.x, fmaf(v.y, v.y, fmaf(v.z, v.z, fmaf(v.w, v.w, s))));
        }
        s += __shfl_xor_sync(0xffffffffu, s, 1);
        s += __shfl_xor_sync(0xffffffffu, s, 2);
        if (sub == 0) {
            float inv = 1.0f / fmaxf(sqrtf(s), EPSV);
            if (rowid < 32) inv_qn_s[rowid] = inv;
            else            inv_wn_s[rowid - 32] = inv;
        }
    }
    __syncthreads();

    // ---- 2x2 register-blocked dot over K=128, interleaved rows ----
    float a00 = 0.f, a01 = 0.f, a10 = 0.f, a11 = 0.f;
#pragma unroll
    for (int k = 0; k < 32; k++) {
        float4 qa = qs[ty     ][k];
        float4 qb = qs[ty + 16][k];
        float4 wa = ws[tx     ][k];
        float4 wb = ws[tx + 16][k];
        a00 = fmaf(qa.x, wa.x, fmaf(qa.y, wa.y, fmaf(qa.z, wa.z, fmaf(qa.w, wa.w, a00))));
        a01 = fmaf(qa.x, wb.x, fmaf(qa.y, wb.y, fmaf(qa.z, wb.z, fmaf(qa.w, wb.w, a01))));
        a10 = fmaf(qb.x, wa.x, fmaf(qb.y, wa.y, fmaf(qb.z, wa.z, fmaf(qb.w, wa.w, a10))));
        a11 = fmaf(qb.x, wb.x, fmaf(qb.y, wb.y, fmaf(qb.z, wb.z, fmaf(qb.w, wb.w, a11))));
    }

    float iq0 = inv_qn_s[ty];
    float iq1 = inv_qn_s[ty + 16];
    float iw0 = inv_wn_s[tx];
    float iw1 = inv_wn_s[tx + 16];

    // outputs: (b0+ty, r0+tx), (b0+ty, r0+tx+16), (+16 b rows)
    size_t base0 = ((size_t)(b0 + ty) * 256 + (r0 + tx)) * 8 + n;
    size_t base1 = base0 + (size_t)16 * 256 * 8;
    g_cs[base0]                = fmaxf(a00 * iq0 * iw0, 0.f);
    g_cs[base0 + 16 * 8]       = fmaxf(a01 * iq0 * iw1, 0.f);
    g_cs[base1]                = fmaxf(a10 * iq1 * iw0, 0.f);
    g_cs[base1 + 16 * 8]       = fmaxf(a11 * iq1 * iw1, 0.f);
}

// ---------------------------------------------------------------------------
// expand kernel: 1024 blocks x 256 threads, block owns 128 consecutive pairs.
// Output mapping per pair: i = s*128 + lane*4 + m  (s in {0,1}, m in 0..3).
//   bit0,1 of i  <- m        (factors 0,1 in the 4-wide tree)
//   bits 2..6    <- lane     (factors 2..6 in 'base')
//   bit7         <- s        (factor 7 picks between the two stores)
// => each STG.128 covers a fully contiguous, full-line 512 B. DRAM-bound.
// ---------------------------------------------------------------------------
__global__ __launch_bounds__(256) void expand_kernel(float* __restrict__ out)
{
    __shared__ float s_cs[128 * 8];

    const int tid  = threadIdx.x;
    const int warp = tid >> 5;
    const int lane = tid & 31;
    const size_t p0 = (size_t)blockIdx.x * 128;   // first pair of this block

    // stage cs slice: 1024 floats = 256 float4, fully coalesced
    ((float4*)s_cs)[tid] = ((const float4*)(g_cs + p0 * 8))[tid];
    __syncthreads();

    const int t2 = (lane >> 0) & 1, t3 = (lane >> 1) & 1, t4 = (lane >> 2) & 1;
    const int t5 = (lane >> 3) & 1, t6 = (lane >> 4) & 1;

    float* outw = out + (p0 + warp * 16) * 256 + lane * 4;

#pragma unroll 4
    for (int j = 0; j < 16; j++) {
        const float* c = &s_cs[(warp * 16 + j) * 8];
        float4 cA = ((const float4*)c)[0];   // broadcast LDS
        float4 cB = ((const float4*)c)[1];

        float cs0 = cA.x, cs1 = cA.y, cs2 = cA.z, cs3 = cA.w;
        float cs4 = cB.x, cs5 = cB.y, cs6 = cB.z, cs7 = cB.w;
        float ms0 = 1.f - cs0, ms1 = 1.f - cs1, ms7 = 1.f - cs7;

        // factors 2..6 selected by lane bits 0..4
        float base = (t2 ? 1.f - cs2 : cs2);
        base *= (t3 ? 1.f - cs3 : cs3);
        base *= (t4 ? 1.f - cs4 : cs4);
        base *= (t5 ? 1.f - cs5 : cs5);
        base *= (t6 ? 1.f - cs6 : cs6);

        // factors 0,1 -> 4-wide tree; factor 7 -> the two stores
        float q0 = cs0 * cs1, q1 = ms0 * cs1, q2 = cs0 * ms1, q3 = ms0 * ms1;
        float b7c = base * cs7, b7m = base * ms7;

        float4 o0, o1;
        o0.x = b7c * q0;  o0.y = b7c * q1;  o0.z = b7c * q2;  o0.w = b7c * q3;
        o1.x = b7m * q0;  o1.y = b7m * q1;  o1.z = b7m * q2;  o1.w = b7m * q3;

        float* dst = outw + (size_t)j * 256;
        __stcs((float4*)dst, o0);             // i = [  0..127]: lane*4
        __stcs((float4*)(dst + 128), o1);     // i = [128..255]: 128 + lane*4
    }
}

extern "C" void kernel_launch(void* const* d_in, const int* in_sizes, int n_in,
                              void* d_out, int out_size) {
    const float* q = (const float*)d_in[0];   // 512 x 1024
    const float* w = (const float*)d_in[1];   // 256 x 1024
    float* out = (float*)d_out;               // 512 x 256 x 256

    cs_kernel<<<dim3(128, 8), 256>>>(q, w);
    expand_kernel<<<1024, 256>>>(out);
}

// round 12
// speedup vs baseline: 1.9829x; 1.1520x over previous
#include <cuda_runtime.h>

#define EPSV 1e-8f

// scratch: cs[b][r][n] = relu(cosine), 4 MB (stays in L2 between kernels)
__device__ __align__(16) float g_cs[512 * 256 * 8];

// ---------------------------------------------------------------------------
// cs kernel: 64b x 64r tile per block, one n per block. Grid (8, 4, 8) = 256.
// 256 threads (16x16), 4x4 register blocking, interleaved sub-rows
// {t, t+16, t+32, t+48}. K=128 staged in two 64-float halves (35 KB smem).
// Row norms accumulated in-register across halves (2 threads per row).
// ---------------------------------------------------------------------------
__global__ __launch_bounds__(256) void cs_kernel(const float* __restrict__ q,
                                                 const float* __restrict__ w)
{
    __shared__ float4 qs[64][17];     // 64 rows x 16 float4 (+1 pad)
    __shared__ float4 ws[64][17];
    __shared__ float inv_qn_s[64];
    __shared__ float inv_wn_s[64];

    const int tid = threadIdx.x;
    const int tx = tid & 15, ty = tid >> 4;
    const int b0 = blockIdx.x * 64;
    const int r0 = blockIdx.y * 64;
    const int n  = blockIdx.z;

    const float4* q4 = (const float4*)q;
    const float4* w4 = (const float4*)w;

    float acc[4][4];
#pragma unroll
    for (int i = 0; i < 4; i++)
#pragma unroll
        for (int j = 0; j < 4; j++) acc[i][j] = 0.f;

    // norm partial: thread covers row = tid>>1 (0-63 q, 64-127 w), slot = tid&1
    const int nrow = tid >> 1;
    const int slot = tid & 1;
    float nsum = 0.f;

    for (int h = 0; h < 2; h++) {
        __syncthreads();
        // ---- stage 64 x 64-float halves of q and w tiles (coalesced) ----
#pragma unroll
        for (int k = 0; k < 4; k++) {
            int idx = tid + 256 * k;
            int row = idx >> 4, col = idx & 15;
            size_t gcol = n * 32 + h * 16 + col;
            qs[row][col] = q4[(size_t)(b0 + row) * 256 + gcol];
            ws[row][col] = w4[(size_t)(r0 + row) * 256 + gcol];
        }
        __syncthreads();

        // ---- norm partials from staged tiles ----
        {
            const float4* src = (nrow < 32) ? &qs[nrow][0] : &ws[nrow - 32][0];
            // rows 0-63 in each array; nrow 0-63 -> q rows 0-63? No:
            // nrow 0..63 covers q rows 0..63 when nrow<64... recompute below.
        }
        {
            const float4* src = (nrow < 64) ? &qs[0][0] : &ws[0][0];
        }
        // (see corrected norm block below)
        {
            const float4* src;
            int r = nrow;
            if (nrow < 64) src = &qs[r][0];
            else         { r = nrow - 64; src = &ws[r][0]; }
            // nrow in [0,128) requires tid>>1 in [0,128): true (tid<256)
            float s = 0.f;
#pragma unroll
            for (int j = 0; j < 8; j++) {
                float4 v = src[slot * 8 + j];
                s = fmaf(v.x, v.x, fmaf(v.y, v.y, fmaf(v.z, v.z, fmaf(v.w, v.w, s))));
            }
            nsum += s;
        }

        // ---- 4x4 register-blocked dot over this K-half ----
#pragma unroll
        for (int k = 0; k < 16; k++) {
            float4 qv[4], wv[4];
#pragma unroll
            for (int i = 0; i < 4; i++) qv[i] = qs[ty + 16 * i][k];
#pragma unroll
            for (int j = 0; j < 4; j++) wv[j] = ws[tx + 16 * j][k];
#pragma unroll
            for (int i = 0; i < 4; i++)
#pragma unroll
                for (int j = 0; j < 4; j++) {
                    acc[i][j] = fmaf(qv[i].x, wv[j].x,
                                fmaf(qv[i].y, wv[j].y,
                                fmaf(qv[i].z, wv[j].z,
                                fmaf(qv[i].w, wv[j].w, acc[i][j]))));
                }
        }
    }

    // ---- finalize norms: combine the two slots, write inverse norms ----
    nsum += __shfl_xor_sync(0xffffffffu, nsum, 1);
    if (slot == 0) {
        float inv = 1.0f / fmaxf(sqrtf(nsum), EPSV);
        if (nrow < 64) inv_qn_s[nrow] = inv;
        else           inv_wn_s[nrow - 64] = inv;
    }
    __syncthreads();

    // ---- scale + relu + store ----
    float iq[4], iw[4];
#pragma unroll
    for (int i = 0; i < 4; i++) iq[i] = inv_qn_s[ty + 16 * i];
#pragma unroll
    for (int j = 0; j < 4; j++) iw[j] = inv_wn_s[tx + 16 * j];

#pragma unroll
    for (int i = 0; i < 4; i++) {
        size_t rowbase = ((size_t)(b0 + ty + 16 * i) * 256 + r0 + tx) * 8 + n;
#pragma unroll
        for (int j = 0; j < 4; j++) {
            g_cs[rowbase + (size_t)(16 * j) * 8] =
                fmaxf(acc[i][j] * iq[i] * iw[j], 0.f);
        }
    }
}

// ---------------------------------------------------------------------------
// expand kernel (unchanged from R10 best): 1024 blocks x 256 threads.
// Output mapping per pair: i = s*128 + lane*4 + m -> fully contiguous STG.128.
// ---------------------------------------------------------------------------
__global__ __launch_bounds__(256) void expand_kernel(float* __restrict__ out)
{
    __shared__ float s_cs[128 * 8];

    const int tid  = threadIdx.x;
    const int warp = tid >> 5;
    const int lane = tid & 31;
    const size_t p0 = (size_t)blockIdx.x * 128;

    ((float4*)s_cs)[tid] = ((const float4*)(g_cs + p0 * 8))[tid];
    __syncthreads();

    const int t2 = (lane >> 0) & 1, t3 = (lane >> 1) & 1, t4 = (lane >> 2) & 1;
    const int t5 = (lane >> 3) & 1, t6 = (lane >> 4) & 1;

    float* outw = out + (p0 + warp * 16) * 256 + lane * 4;

#pragma unroll 4
    for (int j = 0; j < 16; j++) {
        const float* c = &s_cs[(warp * 16 + j) * 8];
        float4 cA = ((const float4*)c)[0];
        float4 cB = ((const float4*)c)[1];

        float cs0 = cA.x, cs1 = cA.y, cs2 = cA.z, cs3 = cA.w;
        float cs4 = cB.x, cs5 = cB.y, cs6 = cB.z, cs7 = cB.w;
        float ms0 = 1.f - cs0, ms1 = 1.f - cs1, ms7 = 1.f - cs7;

        float base = (t2 ? 1.f - cs2 : cs2);
        base *= (t3 ? 1.f - cs3 : cs3);
        base *= (t4 ? 1.f - cs4 : cs4);
        base *= (t5 ? 1.f - cs5 : cs5);
        base *= (t6 ? 1.f - cs6 : cs6);

        float q0 = cs0 * cs1, q1 = ms0 * cs1, q2 = cs0 * ms1, q3 = ms0 * ms1;
        float b7c = base * cs7, b7m = base * ms7;

        float4 o0, o1;
        o0.x = b7c * q0;  o0.y = b7c * q1;  o0.z = b7c * q2;  o0.w = b7c * q3;
        o1.x = b7m * q0;  o1.y = b7m * q1;  o1.z = b7m * q2;  o1.w = b7m * q3;

        float* dst = outw + (size_t)j * 256;
        __stcs((float4*)dst, o0);
        __stcs((float4*)(dst + 128), o1);
    }
}

extern "C" void kernel_launch(void* const* d_in, const int* in_sizes, int n_in,
                              void* d_out, int out_size) {
    const float* q = (const float*)d_in[0];   // 512 x 1024
    const float* w = (const float*)d_in[1];   // 256 x 1024
    float* out = (float*)d_out;               // 512 x 256 x 256

    cs_kernel<<<dim3(8, 4, 8), 256>>>(q, w);
    expand_kernel<<<1024, 256>>>(out);
}